// round 7
// baseline (speedup 1.0000x reference)
#include <cuda_runtime.h>
#include <math.h>

#define NN 3000
#define EE 48000
#define FF 32
#define GRID 148
#define TPB 672            // 21 warps
#define NWARP 21
#define EXCL 1200
#define KSELF 10800.0f
#define ROWCAP 64
#define NRMAX 21
#define NPH 24u            // dataflow phases per run

// ---------------- static global state ----------------
__device__ unsigned int g_gen[(size_t)NN * NN];   // 36 MB dedup generations (never zeroed)
__device__ unsigned int g_run;                     // run epoch
__device__ int g_deg[NN];
__device__ int g_rcnt[NN];
__device__ unsigned short g_cols[NN * ROWCAP];
__device__ float g_P[24][NN * FF];                 // one buffer per phase (9.2 MB, L2-resident)
__device__ unsigned int g_rowep[NN];               // per-row dataflow epochs (monotonic)
__device__ unsigned long long g_keys[NN];
__device__ float g_part[GRID * FF];
__device__ unsigned int g_ctr;                     // ticket barrier counter (monotonic)

// ---------------- ticket barrier (R5 flavor — best measured) ----------------
__device__ __forceinline__ void gsync() {
    __syncthreads();
    if (threadIdx.x == 0) {
        unsigned int old;
        asm volatile("atom.release.gpu.global.add.u32 %0, [%1], 1;"
                     : "=r"(old) : "l"(&g_ctr) : "memory");
        unsigned int target = old - (old % GRID) + GRID;
        unsigned int v;
        do {
            asm volatile("ld.acquire.gpu.global.u32 %0, [%1];" : "=r"(v) : "l"(&g_ctr) : "memory");
        } while ((int)(v - target) < 0);
    }
    __syncthreads();
}

__device__ __forceinline__ unsigned int ld_acq(const unsigned int* p) {
    unsigned int v;
    asm volatile("ld.acquire.gpu.global.u32 %0, [%1];" : "=r"(v) : "l"(p) : "memory");
    return v;
}

__device__ __forceinline__ unsigned int f2ord(float f) {
    unsigned int u = __float_as_uint(f);
    return (u & 0x80000000u) ? ~u : (u | 0x80000000u);
}

// ---------------- the one persistent kernel ----------------
__global__ void __launch_bounds__(TPB, 1)
cayley_all(const float* __restrict__ x, const int* __restrict__ ei,
           const float* __restrict__ ph, const float* __restrict__ palpha,
           const float* __restrict__ Wr0, const float* __restrict__ Wc0a,
           const float* __restrict__ Wc0b, const float* __restrict__ Wr1,
           const float* __restrict__ Wc1a, const float* __restrict__ Wc1b,
           const float* __restrict__ pw, const float* __restrict__ lw,
           const float* __restrict__ lb, float* __restrict__ out) {
    // s_mix: weights (6*4KB=24576B) during phases, then sort keys (24000B) + partials (2688B)
    __shared__ __align__(16) unsigned char s_mix[24576 + NWARP * FF * 4];
    __shared__ __align__(8) float2 s_ew[NRMAX * ROWCAP];
    __shared__ int s_cnt[NRMAX];
    __shared__ float s_sinv[NRMAX];

    const int tid  = threadIdx.x;
    const int lane = tid & 31;
    const int wid  = tid >> 5;
    const int bid  = blockIdx.x;

    const int r0    = (bid < 40) ? bid * 21 : 840 + (bid - 40) * 20;
    const int nrows = (bid < 40) ? 21 : 20;
    const int myrow = r0 + wid;                // valid if wid < nrows

    const unsigned int runv = g_run;           // kernel-boundary safe
    const unsigned int gen  = runv + 1u;
    const unsigned int epbase = runv * NPH;    // rowep base for this run

    const int* rowp = ei;
    const int* colp = ei + EE;
    const float hh = __ldg(ph);
    const float aa = __ldg(palpha);

    // pool_w norm
    float pwv = __ldg(pw + lane);
    float nv = pwv * pwv;
#pragma unroll
    for (int o = 16; o > 0; o >>= 1) nv += __shfl_xor_sync(0xffffffffu, nv, o);
    const float pnorm = sqrtf(nv);

    // ---- stage all 6 weight matrices (transposed) into smem ----
    {
        float* sW = (float*)s_mix;
        for (int t = tid; t < FF * FF; t += TPB) {
            int f = t >> 5, k = t & 31;
            sW[k * FF + f]        = __ldg(Wr0 + t);
            sW[1024 + k * FF + f] = __ldg(Wc0a + t);
            sW[2048 + k * FF + f] = __ldg(Wc0b + t);
            sW[3072 + k * FF + f] = __ldg(Wr1 + t);
            sW[4096 + k * FF + f] = __ldg(Wc1a + t);
            sW[5120 + k * FF + f] = __ldg(Wc1b + t);
        }
    }

    // ---- S1: distributed edge build ----
    {
        int e = bid * TPB + tid;
        if (e < EE) {
            int r = __ldg(rowp + e), c = __ldg(colp + e);
            atomicAdd(&g_deg[r], 1);
            unsigned int old = atomicMax(&g_gen[(size_t)r * NN + c], gen);
            if (old < gen) {
                int pos = atomicAdd(&g_rcnt[r], 1);
                if (pos < ROWCAP) g_cols[r * ROWCAP + pos] = (unsigned short)c;
            }
        }
    }
    gsync();   // GB1 (also covers weight staging)

    // ---- local CSR -> smem ----
    {
        if (tid < nrows) {
            int r = r0 + tid;
            int c2 = g_rcnt[r];
            s_cnt[tid] = c2 > ROWCAP ? ROWCAP : c2;
            s_sinv[tid] = 1.0f / ((float)g_deg[r] - aa);
        }
        __syncthreads();
        for (int idx = tid; idx < NRMAX * ROWCAP; idx += TPB) {
            int lr = idx >> 6, j = idx & 63;
            if (lr < nrows && j < s_cnt[lr]) {
                int c = (int)g_cols[(r0 + lr) * ROWCAP + j];
                float w = 1.0f / (((float)g_deg[c] - aa) * hh);
                s_ew[idx] = make_float2(__int_as_float(c * (FF * 4)), w);
            }
        }
        __syncthreads();
    }

    // per-lane source rows for dataflow waits
    int srcA = -1, srcB = -1, mycnt = 0;
    if (wid < nrows) {
        mycnt = s_cnt[wid];
        if (lane < mycnt)      srcA = __float_as_int(s_ew[wid * ROWCAP + lane].x) >> 7;
        if (lane + 32 < mycnt) srcB = __float_as_int(s_ew[wid * ROWCAP + lane + 32].x) >> 7;
    }

#define WAITP(P) do { if ((P) > 1 && wid < nrows) { \
        unsigned int tgt = epbase + (unsigned int)((P) - 1); \
        bool okA = (srcA < 0), okB = (srcB < 0); \
        for (;;) { \
            if (!okA) okA = ((int)(ld_acq(&g_rowep[srcA]) - tgt) >= 0); \
            if (!okB) okB = ((int)(ld_acq(&g_rowep[srcB]) - tgt) >= 0); \
            if (__all_sync(0xffffffffu, okA && okB)) break; \
        } } } while (0)

#define FLAGP(P) do { if (wid < nrows) { __syncwarp(); if (lane == 0) \
        asm volatile("st.release.gpu.global.u32 [%0], %1;" \
                     :: "l"(&g_rowep[myrow]), "r"(epbase + (unsigned int)(P)) : "memory"); } } while (0)

#define ROW_BJAC(IN, RES) do { \
        float diag = __ldcg((IN) + myrow * FF + lane); \
        const float2* ep = s_ew + wid * ROWCAP; \
        float acc = 0.f; \
        _Pragma("unroll 8") \
        for (int j = 0; j < mycnt; ++j) { \
            float2 e = ep[j]; \
            acc += __ldcg((const float*)((const char*)(IN) + __float_as_int(e.x)) + lane); \
        } \
        RES = diag - s_sinv[wid] * acc; \
    } while (0)

#define ROW_JAC(YK, BJ, RES) do { \
        float bjv = __ldcg((BJ) + myrow * FF + lane); \
        const float2* ep = s_ew + wid * ROWCAP; \
        float acc = 0.f; \
        _Pragma("unroll 8") \
        for (int j = 0; j < mycnt; ++j) { \
            float2 e = ep[j]; \
            acc += e.y * __ldcg((const float*)((const char*)(YK) + __float_as_int(e.x)) + lane); \
        } \
        RES = acc + bjv; \
    } while (0)

#define PH_BJAC(P, IN, OUT) do { WAITP(P); \
        if (wid < nrows) { float rr; ROW_BJAC(IN, rr); (OUT)[myrow * FF + lane] = rr; } \
        FLAGP(P); } while (0)

#define PH_JAC(P, YK, BJ, OUT) do { WAITP(P); \
        if (wid < nrows) { float rr; ROW_JAC(YK, BJ, rr); (OUT)[myrow * FF + lane] = rr; } \
        FLAGP(P); } while (0)

    float myscore = 0.f, myxout = 0.f;
    const float* sW = (const float*)s_mix;

    // ================= dataflow phases (no global barriers) =================
    // layer 0, order 0
    PH_BJAC(1,  x,       g_P[0]);
    PH_JAC (2,  g_P[0],  g_P[0],  g_P[1]);
    PH_JAC (3,  g_P[1],  g_P[0],  g_P[2]);
    PH_JAC (4,  g_P[2],  g_P[0],  g_P[3]);
    PH_JAC (5,  g_P[3],  g_P[0],  g_P[4]);
    PH_JAC (6,  g_P[4],  g_P[0],  g_P[5]);     // Y1 (layer0)
    // layer 0, order 1
    PH_BJAC(7,  g_P[5],  g_P[6]);
    PH_JAC (8,  g_P[6],  g_P[6],  g_P[7]);
    PH_JAC (9,  g_P[7],  g_P[6],  g_P[8]);
    PH_JAC (10, g_P[8],  g_P[6],  g_P[9]);
    PH_JAC (11, g_P[9],  g_P[6],  g_P[10]);
    // phase 12: fused last jac + outgemm -> X1 (g_P[11])
    {
        WAITP(12);
        if (wid < nrows) {
            float y2; ROW_JAC(g_P[10], g_P[6], y2);
            float y1 = __ldcg(g_P[5] + myrow * FF + lane);
            float xo = __ldg(x + myrow * FF + lane);
            float acc = 0.f;
#pragma unroll
            for (int k = 0; k < FF; ++k) {
                float xv  = __shfl_sync(0xffffffffu, xo, k);
                float y1v = __shfl_sync(0xffffffffu, y1, k);
                float y2v = __shfl_sync(0xffffffffu, y2, k);
                acc += xv * sW[k * FF + lane]
                     + 2.f * y1v * sW[1024 + k * FF + lane]
                     + 2.f * y2v * sW[2048 + k * FF + lane];
            }
            g_P[11][myrow * FF + lane] = fmaxf(acc, 0.f);
        }
        FLAGP(12);
    }
    // layer 1, order 0
    PH_BJAC(13, g_P[11], g_P[12]);
    PH_JAC (14, g_P[12], g_P[12], g_P[13]);
    PH_JAC (15, g_P[13], g_P[12], g_P[14]);
    PH_JAC (16, g_P[14], g_P[12], g_P[15]);
    PH_JAC (17, g_P[15], g_P[12], g_P[16]);
    PH_JAC (18, g_P[16], g_P[12], g_P[17]);    // Y1 (layer1)
    // layer 1, order 1
    PH_BJAC(19, g_P[17], g_P[18]);
    PH_JAC (20, g_P[18], g_P[18], g_P[19]);
    PH_JAC (21, g_P[19], g_P[18], g_P[20]);
    PH_JAC (22, g_P[20], g_P[18], g_P[21]);
    PH_JAC (23, g_P[21], g_P[18], g_P[22]);
    // phase 24: fused last jac + outgemm + score/keys (X2 in registers)
    {
        WAITP(24);
        if (wid < nrows) {
            float y2; ROW_JAC(g_P[22], g_P[18], y2);
            float y1 = __ldcg(g_P[17] + myrow * FF + lane);
            float xo = __ldcg(g_P[11] + myrow * FF + lane);
            float acc = 0.f;
#pragma unroll
            for (int k = 0; k < FF; ++k) {
                float xv  = __shfl_sync(0xffffffffu, xo, k);
                float y1v = __shfl_sync(0xffffffffu, y1, k);
                float y2v = __shfl_sync(0xffffffffu, y2, k);
                acc += xv * sW[3072 + k * FF + lane]
                     + 2.f * y1v * sW[4096 + k * FF + lane]
                     + 2.f * y2v * sW[5120 + k * FF + lane];
            }
            myxout = fmaxf(acc, 0.f);
            float v = myxout * pwv;
#pragma unroll
            for (int o = 16; o > 0; o >>= 1) v += __shfl_xor_sync(0xffffffffu, v, o);
            myscore = tanhf(v / pnorm);
            if (lane == 0)
                g_keys[myrow] = ((unsigned long long)f2ord(myscore) << 32)
                              | (unsigned long long)(0xFFFFFFFFu - (unsigned int)myrow);
        }
        FLAGP(24);
    }
    gsync();   // GB2: all keys visible

    // ---- rank + weighted partial sums + counter re-zero ----
    {
        unsigned long long* sk = (unsigned long long*)s_mix;     // weights dead now
        float* spart = (float*)(s_mix + 24576);
        for (int i = tid; i < NN; i += TPB)
            sk[i] = __ldcg((const unsigned long long*)(g_keys + i));
        if (tid < nrows) { g_deg[r0 + tid] = 0; g_rcnt[r0 + tid] = 0; }
        __syncthreads();
        float contrib = 0.f;
        if (wid < nrows) {
            unsigned long long ki = ((unsigned long long)f2ord(myscore) << 32)
                                  | (unsigned long long)(0xFFFFFFFFu - (unsigned int)myrow);
            int c2 = 0;
            for (int j = lane; j < NN; j += 32) c2 += (sk[j] < ki) ? 1 : 0;
#pragma unroll
            for (int o = 16; o > 0; o >>= 1) c2 += __shfl_xor_sync(0xffffffffu, c2, o);
            float coef = (c2 < EXCL && myscore < 0.f) ? 0.f : myscore;
            contrib = coef * myxout;
        }
        spart[wid * FF + lane] = contrib;
        __syncthreads();
        if (wid == 0) {
            float t = 0.f;
#pragma unroll
            for (int q = 0; q < NWARP; ++q) t += spart[q * FF + lane];
            g_part[bid * FF + lane] = t;
        }
        gsync();   // GB3
    }

    // ---- block 0: final reduce + linear + run-epoch bump ----
    if (bid == 0) {
        float* spart = (float*)(s_mix + 24576);
        float a = 0.f;
        for (int b = wid; b < GRID; b += NWARP) a += __ldcg(g_part + b * FF + lane);
        spart[wid * FF + lane] = a;
        __syncthreads();
        if (wid == 0) {
            float t = 0.f;
#pragma unroll
            for (int q = 0; q < NWARP; ++q) t += spart[q * FF + lane];
            spart[lane] = t * (1.0f / KSELF);
            __syncwarp();
            if (lane < 8) {
                float o = __ldg(lb + lane);
#pragma unroll
                for (int f = 0; f < FF; ++f) o += spart[f] * __ldg(lw + lane * FF + f);
                out[lane] = o;
            }
            if (lane == 0) g_run = gen;
        }
    }
}

// ---------------- host side ----------------
extern "C" void kernel_launch(void* const* d_in, const int* in_sizes, int n_in,
                              void* d_out, int out_size) {
    const float* x     = (const float*)d_in[0];
    const int*   ei    = (const int*)d_in[1];
    const float* h     = (const float*)d_in[2];
    const float* alpha = (const float*)d_in[3];
    const float* Wr0   = (const float*)d_in[4];
    const float* Wc0a  = (const float*)d_in[5];
    const float* Wc0b  = (const float*)d_in[6];
    const float* Wr1   = (const float*)d_in[7];
    const float* Wc1a  = (const float*)d_in[8];
    const float* Wc1b  = (const float*)d_in[9];
    const float* pw    = (const float*)d_in[10];
    const float* lw    = (const float*)d_in[11];
    const float* lb    = (const float*)d_in[12];

    cayley_all<<<GRID, TPB>>>(x, ei, h, alpha, Wr0, Wc0a, Wc0b,
                              Wr1, Wc1a, Wc1b, pw, lw, lb, (float*)d_out);
}

// round 8
// speedup vs baseline: 1.4367x; 1.4367x over previous
#include <cuda_runtime.h>
#include <math.h>

#define NN 3000
#define EE 48000
#define FF 32
#define GRID 148
#define TPB 672            // 21 warps
#define NWARP 21
#define EXCL 1200
#define KSELF 10800.0f
#define ROWCAP 64
#define NRMAX 21
#define NBAR 26u
#define NG 12              // barrier tree groups

// ---------------- static global state ----------------
__device__ unsigned int g_gen[(size_t)NN * NN];   // 36 MB dedup generations (never zeroed)
__device__ unsigned int g_run;                     // run epoch
__device__ int g_deg[NN];
__device__ int g_rcnt[NN];
__device__ unsigned short g_cols[NN * ROWCAP];
__device__ float g_A[NN * FF];
__device__ float g_B[NN * FF];
__device__ float g_C[NN * FF];
__device__ float g_Y1[NN * FF];
__device__ float g_X1[NN * FF];
__device__ unsigned long long g_keys[NN];
__device__ float g_part[GRID * FF];
__device__ unsigned int g_ctr1[NG * 32];           // group counters, 128B strided
__device__ unsigned int g_ctr2[32];                // root counter (own line)
__device__ unsigned int g_flagv[32];               // release flag (own line)

// ---------------- two-level tree barrier ----------------
__device__ __forceinline__ void gsync(unsigned int epoch, int grp, unsigned int gsz) {
    __syncthreads();
    if (threadIdx.x == 0) {
        unsigned int old;
        asm volatile("atom.acq_rel.gpu.global.add.u32 %0, [%1], 1;"
                     : "=r"(old) : "l"(&g_ctr1[grp * 32]) : "memory");
        bool iam_release = false;
        if (old % gsz == gsz - 1u) {                       // last of my group
            unsigned int o2;
            asm volatile("atom.acq_rel.gpu.global.add.u32 %0, [%1], 1;"
                         : "=r"(o2) : "l"(&g_ctr2[0]) : "memory");
            if (o2 % NG == NG - 1u) {                      // last group
                asm volatile("st.release.gpu.global.u32 [%0], %1;"
                             :: "l"(&g_flagv[0]), "r"(epoch) : "memory");
                iam_release = true;
            }
        }
        if (!iam_release) {
            unsigned int v;
            do {
                asm volatile("ld.acquire.gpu.global.u32 %0, [%1];"
                             : "=r"(v) : "l"(&g_flagv[0]) : "memory");
            } while ((int)(v - epoch) < 0);
        }
    }
    __syncthreads();
}

__device__ __forceinline__ unsigned int f2ord(float f) {
    unsigned int u = __float_as_uint(f);
    return (u & 0x80000000u) ? ~u : (u | 0x80000000u);
}

// ---------------- the one persistent kernel ----------------
__global__ void __launch_bounds__(TPB, 1)
cayley_all(const float* __restrict__ x, const int* __restrict__ ei,
           const float* __restrict__ ph, const float* __restrict__ palpha,
           const float* __restrict__ Wr0, const float* __restrict__ Wc0a,
           const float* __restrict__ Wc0b, const float* __restrict__ Wr1,
           const float* __restrict__ Wc1a, const float* __restrict__ Wc1b,
           const float* __restrict__ pw, const float* __restrict__ lw,
           const float* __restrict__ lb, float* __restrict__ out) {
    __shared__ __align__(16) unsigned char s_raw[24000 + NWARP * FF * 4];  // keys / sW / partials
    __shared__ __align__(8) float2 s_ew[NRMAX * ROWCAP];
    __shared__ int s_cnt[NRMAX];
    __shared__ float s_sinv[NRMAX];

    const int tid  = threadIdx.x;
    const int lane = tid & 31;
    const int wid  = tid >> 5;
    const int bid  = blockIdx.x;

    // balanced rows: blocks 0..39 get 21, 40..147 get 20
    const int r0    = (bid < 40) ? bid * 21 : 840 + (bid - 40) * 20;
    const int nrows = (bid < 40) ? 21 : 20;

    // barrier tree group: groups 0..3 have 13 blocks, groups 4..11 have 12
    const int grp = (bid < 52) ? (bid / 13) : (4 + (bid - 52) / 12);
    const unsigned int gsz = (bid < 52) ? 13u : 12u;

    const unsigned int runv = g_run;          // kernel-boundary safe
    const unsigned int gen  = runv + 1u;
    unsigned int epoch = runv * NBAR;

    const int* rowp = ei;
    const int* colp = ei + EE;
    const float hh = __ldg(ph);
    const float aa = __ldg(palpha);

    // pool_w norm
    float pwv = __ldg(pw + lane);
    float nv = pwv * pwv;
#pragma unroll
    for (int o = 16; o > 0; o >>= 1) nv += __shfl_xor_sync(0xffffffffu, nv, o);
    const float pnorm = sqrtf(nv);

    // ---- S1: distributed edge build (1 edge / thread) ----
    {
        int e = bid * TPB + tid;
        if (e < EE) {
            int r = __ldg(rowp + e), c = __ldg(colp + e);
            atomicAdd(&g_deg[r], 1);
            unsigned int old = atomicMax(&g_gen[(size_t)r * NN + c], gen);
            if (old < gen) {
                int pos = atomicAdd(&g_rcnt[r], 1);
                if (pos < ROWCAP) g_cols[r * ROWCAP + pos] = (unsigned short)c;
            }
        }
    }
    gsync(++epoch, grp, gsz);   // B1

    // ---- CSR -> smem + weights ----
    {
        if (tid < nrows) {
            int r = r0 + tid;
            int c2 = g_rcnt[r];
            s_cnt[tid] = c2 > ROWCAP ? ROWCAP : c2;
            s_sinv[tid] = 1.0f / ((float)g_deg[r] - aa);
        }
        __syncthreads();
        for (int idx = tid; idx < NRMAX * ROWCAP; idx += TPB) {
            int lr = idx >> 6, j = idx & 63;
            if (lr < nrows && j < s_cnt[lr]) {
                int c = (int)g_cols[(r0 + lr) * ROWCAP + j];
                float w = 1.0f / (((float)g_deg[c] - aa) * hh);
                s_ew[idx] = make_float2(__int_as_float(c * (FF * 4)), w);
            }
        }
        __syncthreads();
    }

#define ROW_BJAC(IN, RES) do { \
        int r = r0 + wid; \
        float diag = __ldcg((IN) + r * FF + lane); \
        int cnt = s_cnt[wid]; \
        const float2* ep = s_ew + wid * ROWCAP; \
        float acc = 0.f; \
        _Pragma("unroll 8") \
        for (int j = 0; j < cnt; ++j) { \
            float2 e = ep[j]; \
            acc += __ldcg((const float*)((const char*)(IN) + __float_as_int(e.x)) + lane); \
        } \
        RES = diag - s_sinv[wid] * acc; \
    } while (0)

#define ROW_JAC(YK, BJ, RES) do { \
        int r = r0 + wid; \
        float bjv = __ldcg((BJ) + r * FF + lane); \
        int cnt = s_cnt[wid]; \
        const float2* ep = s_ew + wid * ROWCAP; \
        float acc = 0.f; \
        _Pragma("unroll 8") \
        for (int j = 0; j < cnt; ++j) { \
            float2 e = ep[j]; \
            acc += e.y * __ldcg((const float*)((const char*)(YK) + __float_as_int(e.x)) + lane); \
        } \
        RES = acc + bjv; \
    } while (0)

#define PHASE_BJAC(IN, OUT) do { \
        if (wid < nrows) { float rres; ROW_BJAC(IN, rres); \
            __stcg(&OUT[(r0 + wid) * FF + lane], rres); } \
        gsync(++epoch, grp, gsz); } while (0)

#define PHASE_JAC(YK, BJ, OUT) do { \
        if (wid < nrows) { float rres; ROW_JAC(YK, BJ, rres); \
            __stcg(&OUT[(r0 + wid) * FF + lane], rres); } \
        gsync(++epoch, grp, gsz); } while (0)

    float myscore = 0.f, myxout = 0.f;

    // ---- layer 0 order 0 ----
    PHASE_BJAC(x, g_A);            // B2
    PHASE_JAC(g_A, g_A, g_B);      // B3
    PHASE_JAC(g_B, g_A, g_C);      // B4
    PHASE_JAC(g_C, g_A, g_B);      // B5
    PHASE_JAC(g_B, g_A, g_C);      // B6
    PHASE_JAC(g_C, g_A, g_Y1);     // B7

    // ---- layer 0 order 1 ----
    PHASE_BJAC(g_Y1, g_A);         // B8
    PHASE_JAC(g_A, g_A, g_B);      // B9
    PHASE_JAC(g_B, g_A, g_C);      // B10
    PHASE_JAC(g_C, g_A, g_B);      // B11
    PHASE_JAC(g_B, g_A, g_C);      // B12
    // fused last jac + outgemm -> X1
    {
        float* sW = (float*)s_raw;
        for (int t = tid; t < FF * FF; t += TPB) {
            int f = t >> 5, k = t & 31;
            sW[k * FF + f]        = __ldg(Wr0 + t);
            sW[1024 + k * FF + f] = __ldg(Wc0a + t);
            sW[2048 + k * FF + f] = __ldg(Wc0b + t);
        }
        __syncthreads();
        if (wid < nrows) {
            int r = r0 + wid;
            float y2; ROW_JAC(g_C, g_A, y2);
            float y1 = __ldcg(g_Y1 + r * FF + lane);
            float xo = __ldg(x + r * FF + lane);
            float acc = 0.f;
#pragma unroll
            for (int k = 0; k < FF; ++k) {
                float xv  = __shfl_sync(0xffffffffu, xo, k);
                float y1v = __shfl_sync(0xffffffffu, y1, k);
                float y2v = __shfl_sync(0xffffffffu, y2, k);
                acc += xv * sW[k * FF + lane]
                     + 2.f * y1v * sW[1024 + k * FF + lane]
                     + 2.f * y2v * sW[2048 + k * FF + lane];
            }
            __stcg(&g_X1[r * FF + lane], fmaxf(acc, 0.f));
        }
        gsync(++epoch, grp, gsz);   // B13
    }

    // ---- layer 1 order 0 ----
    PHASE_BJAC(g_X1, g_A);         // B14
    PHASE_JAC(g_A, g_A, g_B);      // B15
    PHASE_JAC(g_B, g_A, g_C);      // B16
    PHASE_JAC(g_C, g_A, g_B);      // B17
    PHASE_JAC(g_B, g_A, g_C);      // B18
    PHASE_JAC(g_C, g_A, g_Y1);     // B19

    // ---- layer 1 order 1 ----
    PHASE_BJAC(g_Y1, g_A);         // B20
    PHASE_JAC(g_A, g_A, g_B);      // B21
    PHASE_JAC(g_B, g_A, g_C);      // B22
    PHASE_JAC(g_C, g_A, g_B);      // B23
    PHASE_JAC(g_B, g_A, g_C);      // B24
    // fused last jac + outgemm + score/keys
    {
        float* sW = (float*)s_raw;
        for (int t = tid; t < FF * FF; t += TPB) {
            int f = t >> 5, k = t & 31;
            sW[k * FF + f]        = __ldg(Wr1 + t);
            sW[1024 + k * FF + f] = __ldg(Wc1a + t);
            sW[2048 + k * FF + f] = __ldg(Wc1b + t);
        }
        __syncthreads();
        if (wid < nrows) {
            int r = r0 + wid;
            float y2; ROW_JAC(g_C, g_A, y2);
            float y1 = __ldcg(g_Y1 + r * FF + lane);
            float xo = __ldcg(g_X1 + r * FF + lane);
            float acc = 0.f;
#pragma unroll
            for (int k = 0; k < FF; ++k) {
                float xv  = __shfl_sync(0xffffffffu, xo, k);
                float y1v = __shfl_sync(0xffffffffu, y1, k);
                float y2v = __shfl_sync(0xffffffffu, y2, k);
                acc += xv * sW[k * FF + lane]
                     + 2.f * y1v * sW[1024 + k * FF + lane]
                     + 2.f * y2v * sW[2048 + k * FF + lane];
            }
            myxout = fmaxf(acc, 0.f);
            float v = myxout * pwv;
#pragma unroll
            for (int o = 16; o > 0; o >>= 1) v += __shfl_xor_sync(0xffffffffu, v, o);
            myscore = tanhf(v / pnorm);
            if (lane == 0)
                __stcg((unsigned long long*)&g_keys[r],
                       ((unsigned long long)f2ord(myscore) << 32)
                     | (unsigned long long)(0xFFFFFFFFu - (unsigned int)r));
        }
        gsync(++epoch, grp, gsz);   // B25
    }

    // ---- rank + weighted partial sums + counter re-zero for next run ----
    {
        unsigned long long* sk = (unsigned long long*)s_raw;
        float* spart = (float*)(s_raw + 24000);
        for (int i = tid; i < NN; i += TPB)
            sk[i] = __ldcg((const unsigned long long*)(g_keys + i));
        if (tid < nrows) { g_deg[r0 + tid] = 0; g_rcnt[r0 + tid] = 0; }
        __syncthreads();
        float contrib = 0.f;
        if (wid < nrows) {
            int r = r0 + wid;
            unsigned long long ki = ((unsigned long long)f2ord(myscore) << 32)
                                  | (unsigned long long)(0xFFFFFFFFu - (unsigned int)r);
            int c2 = 0;
            for (int j = lane; j < NN; j += 32) c2 += (sk[j] < ki) ? 1 : 0;
#pragma unroll
            for (int o = 16; o > 0; o >>= 1) c2 += __shfl_xor_sync(0xffffffffu, c2, o);
            float coef = (c2 < EXCL && myscore < 0.f) ? 0.f : myscore;
            contrib = coef * myxout;
        }
        spart[wid * FF + lane] = contrib;
        __syncthreads();
        if (wid == 0) {
            float t = 0.f;
#pragma unroll
            for (int q = 0; q < NWARP; ++q) t += spart[q * FF + lane];
            __stcg(&g_part[bid * FF + lane], t);
        }
        gsync(++epoch, grp, gsz);   // B26
    }

    // ---- block 0: final reduce + linear + run-epoch bump ----
    if (bid == 0) {
        float* spart = (float*)(s_raw + 24000);
        float a = 0.f;
        for (int b = wid; b < GRID; b += NWARP) a += __ldcg(g_part + b * FF + lane);
        spart[wid * FF + lane] = a;
        __syncthreads();
        if (wid == 0) {
            float t = 0.f;
#pragma unroll
            for (int q = 0; q < NWARP; ++q) t += spart[q * FF + lane];
            spart[lane] = t * (1.0f / KSELF);
            __syncwarp();
            if (lane < 8) {
                float o = __ldg(lb + lane);
#pragma unroll
                for (int f = 0; f < FF; ++f) o += spart[f] * __ldg(lw + lane * FF + f);
                out[lane] = o;
            }
            if (lane == 0) g_run = gen;
        }
    }
}

// ---------------- host side ----------------
extern "C" void kernel_launch(void* const* d_in, const int* in_sizes, int n_in,
                              void* d_out, int out_size) {
    const float* x     = (const float*)d_in[0];
    const int*   ei    = (const int*)d_in[1];
    const float* h     = (const float*)d_in[2];
    const float* alpha = (const float*)d_in[3];
    const float* Wr0   = (const float*)d_in[4];
    const float* Wc0a  = (const float*)d_in[5];
    const float* Wc0b  = (const float*)d_in[6];
    const float* Wr1   = (const float*)d_in[7];
    const float* Wc1a  = (const float*)d_in[8];
    const float* Wc1b  = (const float*)d_in[9];
    const float* pw    = (const float*)d_in[10];
    const float* lw    = (const float*)d_in[11];
    const float* lb    = (const float*)d_in[12];

    cayley_all<<<GRID, TPB>>>(x, ei, h, alpha, Wr0, Wc0a, Wc0b,
                              Wr1, Wc1a, Wc1b, pw, lw, lb, (float*)d_out);
}

// round 9
// speedup vs baseline: 1.9567x; 1.3620x over previous
#include <cuda_runtime.h>
#include <math.h>

#define NN 3000
#define EE 48000
#define FF 32
#define GRID 148
#define TPB 672            // 21 warps
#define NWARP 21
#define EXCL 1200
#define KSELF 10800.0f
#define ROWCAP 64
#define NRMAX 21
#define NBAR 26u
#define NLINES 8           // barrier arrival lines

// ---------------- static global state ----------------
__device__ unsigned int g_gen[(size_t)NN * NN];   // 36 MB dedup generations (never zeroed)
__device__ unsigned int g_run;                     // run epoch
__device__ int g_deg[NN];
__device__ int g_rcnt[NN];
__device__ unsigned short g_cols[NN * ROWCAP];
__device__ float g_A[NN * FF];
__device__ float g_B[NN * FF];
__device__ float g_C[NN * FF];
__device__ float g_Y1[NN * FF];
__device__ float g_X1[NN * FF];
__device__ unsigned long long g_keys[NN];
__device__ float g_part[GRID * FF];
__device__ unsigned int g_ctrs[NLINES * 32];       // 8 arrival counters, 128B strided, monotonic

// ---------------- barrier: striped arrivals, warp-parallel summed poll ----------------
__device__ __forceinline__ void gsync(unsigned int epoch) {
    __syncthreads();
    if (threadIdx.x < 32) {
        const int lane = threadIdx.x;
        if (lane == 0) {
            unsigned int old;
            asm volatile("atom.acq_rel.gpu.global.add.u32 %0, [%1], 1;"
                         : "=r"(old) : "l"(&g_ctrs[(blockIdx.x & (NLINES - 1)) * 32]) : "memory");
        }
        const unsigned int target = epoch * GRID;
        for (;;) {
            unsigned int v = 0;
            if (lane < NLINES)
                asm volatile("ld.acquire.gpu.global.u32 %0, [%1];"
                             : "=r"(v) : "l"(&g_ctrs[lane * 32]) : "memory");
            v += __shfl_xor_sync(0xffffffffu, v, 1);
            v += __shfl_xor_sync(0xffffffffu, v, 2);
            v += __shfl_xor_sync(0xffffffffu, v, 4);
            unsigned int total = __shfl_sync(0xffffffffu, v, 0);
            if ((int)(total - target) >= 0) break;
        }
    }
    __syncthreads();
}

__device__ __forceinline__ unsigned int f2ord(float f) {
    unsigned int u = __float_as_uint(f);
    return (u & 0x80000000u) ? ~u : (u | 0x80000000u);
}

// ---------------- the one persistent kernel ----------------
__global__ void __launch_bounds__(TPB, 1)
cayley_all(const float* __restrict__ x, const int* __restrict__ ei,
           const float* __restrict__ ph, const float* __restrict__ palpha,
           const float* __restrict__ Wr0, const float* __restrict__ Wc0a,
           const float* __restrict__ Wc0b, const float* __restrict__ Wr1,
           const float* __restrict__ Wc1a, const float* __restrict__ Wc1b,
           const float* __restrict__ pw, const float* __restrict__ lw,
           const float* __restrict__ lb, float* __restrict__ out) {
    __shared__ __align__(16) unsigned char s_raw[24000 + NWARP * FF * 4];  // keys / sW / partials
    __shared__ __align__(8) float2 s_ew[NRMAX * ROWCAP];
    __shared__ int s_cnt[NRMAX];
    __shared__ float s_sinv[NRMAX];

    const int tid  = threadIdx.x;
    const int lane = tid & 31;
    const int wid  = tid >> 5;
    const int bid  = blockIdx.x;

    // balanced rows: blocks 0..39 get 21, 40..147 get 20
    const int r0    = (bid < 40) ? bid * 21 : 840 + (bid - 40) * 20;
    const int nrows = (bid < 40) ? 21 : 20;

    const unsigned int runv = g_run;          // kernel-boundary safe
    const unsigned int gen  = runv + 1u;
    unsigned int epoch = runv * NBAR;

    const int* rowp = ei;
    const int* colp = ei + EE;
    const float hh = __ldg(ph);
    const float aa = __ldg(palpha);

    // pool_w norm
    float pwv = __ldg(pw + lane);
    float nv = pwv * pwv;
#pragma unroll
    for (int o = 16; o > 0; o >>= 1) nv += __shfl_xor_sync(0xffffffffu, nv, o);
    const float pnorm = sqrtf(nv);

    // ---- S1: distributed edge build (1 edge / thread) ----
    {
        int e = bid * TPB + tid;
        if (e < EE) {
            int r = __ldg(rowp + e), c = __ldg(colp + e);
            atomicAdd(&g_deg[r], 1);
            unsigned int old = atomicMax(&g_gen[(size_t)r * NN + c], gen);
            if (old < gen) {
                int pos = atomicAdd(&g_rcnt[r], 1);
                if (pos < ROWCAP) g_cols[r * ROWCAP + pos] = (unsigned short)c;
            }
        }
    }
    gsync(++epoch);   // B1

    // ---- CSR -> smem + weights ----
    {
        if (tid < nrows) {
            int r = r0 + tid;
            int c2 = g_rcnt[r];
            s_cnt[tid] = c2 > ROWCAP ? ROWCAP : c2;
            s_sinv[tid] = 1.0f / ((float)g_deg[r] - aa);
        }
        __syncthreads();
        for (int idx = tid; idx < NRMAX * ROWCAP; idx += TPB) {
            int lr = idx >> 6, j = idx & 63;
            if (lr < nrows && j < s_cnt[lr]) {
                int c = (int)g_cols[(r0 + lr) * ROWCAP + j];
                float w = 1.0f / (((float)g_deg[c] - aa) * hh);
                s_ew[idx] = make_float2(__int_as_float(c * (FF * 4)), w);
            }
        }
        __syncthreads();
    }

#define ROW_BJAC(IN, RES) do { \
        int r = r0 + wid; \
        float diag = __ldcg((IN) + r * FF + lane); \
        int cnt = s_cnt[wid]; \
        const float2* ep = s_ew + wid * ROWCAP; \
        float acc = 0.f; \
        _Pragma("unroll 8") \
        for (int j = 0; j < cnt; ++j) { \
            float2 e = ep[j]; \
            acc += __ldcg((const float*)((const char*)(IN) + __float_as_int(e.x)) + lane); \
        } \
        RES = diag - s_sinv[wid] * acc; \
    } while (0)

#define ROW_JAC(YK, BJ, RES) do { \
        int r = r0 + wid; \
        float bjv = __ldcg((BJ) + r * FF + lane); \
        int cnt = s_cnt[wid]; \
        const float2* ep = s_ew + wid * ROWCAP; \
        float acc = 0.f; \
        _Pragma("unroll 8") \
        for (int j = 0; j < cnt; ++j) { \
            float2 e = ep[j]; \
            acc += e.y * __ldcg((const float*)((const char*)(YK) + __float_as_int(e.x)) + lane); \
        } \
        RES = acc + bjv; \
    } while (0)

#define PHASE_BJAC(IN, OUT) do { \
        if (wid < nrows) { float rres; ROW_BJAC(IN, rres); \
            OUT[(r0 + wid) * FF + lane] = rres; } \
        gsync(++epoch); } while (0)

#define PHASE_JAC(YK, BJ, OUT) do { \
        if (wid < nrows) { float rres; ROW_JAC(YK, BJ, rres); \
            OUT[(r0 + wid) * FF + lane] = rres; } \
        gsync(++epoch); } while (0)

    float myscore = 0.f, myxout = 0.f;

    // ---- layer 0 order 0 ----
    PHASE_BJAC(x, g_A);            // B2
    PHASE_JAC(g_A, g_A, g_B);      // B3
    PHASE_JAC(g_B, g_A, g_C);      // B4
    PHASE_JAC(g_C, g_A, g_B);      // B5
    PHASE_JAC(g_B, g_A, g_C);      // B6
    PHASE_JAC(g_C, g_A, g_Y1);     // B7

    // ---- layer 0 order 1 ----
    PHASE_BJAC(g_Y1, g_A);         // B8
    PHASE_JAC(g_A, g_A, g_B);      // B9
    PHASE_JAC(g_B, g_A, g_C);      // B10
    PHASE_JAC(g_C, g_A, g_B);      // B11
    PHASE_JAC(g_B, g_A, g_C);      // B12
    // fused last jac + outgemm -> X1
    {
        float* sW = (float*)s_raw;
        for (int t = tid; t < FF * FF; t += TPB) {
            int f = t >> 5, k = t & 31;
            sW[k * FF + f]        = __ldg(Wr0 + t);
            sW[1024 + k * FF + f] = __ldg(Wc0a + t);
            sW[2048 + k * FF + f] = __ldg(Wc0b + t);
        }
        __syncthreads();
        if (wid < nrows) {
            int r = r0 + wid;
            float y2; ROW_JAC(g_C, g_A, y2);
            float y1 = __ldcg(g_Y1 + r * FF + lane);
            float xo = __ldg(x + r * FF + lane);
            float acc = 0.f;
#pragma unroll
            for (int k = 0; k < FF; ++k) {
                float xv  = __shfl_sync(0xffffffffu, xo, k);
                float y1v = __shfl_sync(0xffffffffu, y1, k);
                float y2v = __shfl_sync(0xffffffffu, y2, k);
                acc += xv * sW[k * FF + lane]
                     + 2.f * y1v * sW[1024 + k * FF + lane]
                     + 2.f * y2v * sW[2048 + k * FF + lane];
            }
            g_X1[r * FF + lane] = fmaxf(acc, 0.f);
        }
        gsync(++epoch);   // B13
    }

    // ---- layer 1 order 0 ----
    PHASE_BJAC(g_X1, g_A);         // B14
    PHASE_JAC(g_A, g_A, g_B);      // B15
    PHASE_JAC(g_B, g_A, g_C);      // B16
    PHASE_JAC(g_C, g_A, g_B);      // B17
    PHASE_JAC(g_B, g_A, g_C);      // B18
    PHASE_JAC(g_C, g_A, g_Y1);     // B19

    // ---- layer 1 order 1 ----
    PHASE_BJAC(g_Y1, g_A);         // B20
    PHASE_JAC(g_A, g_A, g_B);      // B21
    PHASE_JAC(g_B, g_A, g_C);      // B22
    PHASE_JAC(g_C, g_A, g_B);      // B23
    PHASE_JAC(g_B, g_A, g_C);      // B24
    // fused last jac + outgemm + score/keys
    {
        float* sW = (float*)s_raw;
        for (int t = tid; t < FF * FF; t += TPB) {
            int f = t >> 5, k = t & 31;
            sW[k * FF + f]        = __ldg(Wr1 + t);
            sW[1024 + k * FF + f] = __ldg(Wc1a + t);
            sW[2048 + k * FF + f] = __ldg(Wc1b + t);
        }
        __syncthreads();
        if (wid < nrows) {
            int r = r0 + wid;
            float y2; ROW_JAC(g_C, g_A, y2);
            float y1 = __ldcg(g_Y1 + r * FF + lane);
            float xo = __ldcg(g_X1 + r * FF + lane);
            float acc = 0.f;
#pragma unroll
            for (int k = 0; k < FF; ++k) {
                float xv  = __shfl_sync(0xffffffffu, xo, k);
                float y1v = __shfl_sync(0xffffffffu, y1, k);
                float y2v = __shfl_sync(0xffffffffu, y2, k);
                acc += xv * sW[k * FF + lane]
                     + 2.f * y1v * sW[1024 + k * FF + lane]
                     + 2.f * y2v * sW[2048 + k * FF + lane];
            }
            myxout = fmaxf(acc, 0.f);
            float v = myxout * pwv;
#pragma unroll
            for (int o = 16; o > 0; o >>= 1) v += __shfl_xor_sync(0xffffffffu, v, o);
            myscore = tanhf(v / pnorm);
            if (lane == 0)
                g_keys[r] = ((unsigned long long)f2ord(myscore) << 32)
                          | (unsigned long long)(0xFFFFFFFFu - (unsigned int)r);
        }
        gsync(++epoch);   // B25
    }

    // ---- rank + weighted partial sums + counter re-zero for next run ----
    {
        unsigned long long* sk = (unsigned long long*)s_raw;
        float* spart = (float*)(s_raw + 24000);
        for (int i = tid; i < NN; i += TPB)
            sk[i] = __ldcg((const unsigned long long*)(g_keys + i));
        if (tid < nrows) { g_deg[r0 + tid] = 0; g_rcnt[r0 + tid] = 0; }
        __syncthreads();
        float contrib = 0.f;
        if (wid < nrows) {
            int r = r0 + wid;
            unsigned long long ki = ((unsigned long long)f2ord(myscore) << 32)
                                  | (unsigned long long)(0xFFFFFFFFu - (unsigned int)r);
            int c2 = 0;
            for (int j = lane; j < NN; j += 32) c2 += (sk[j] < ki) ? 1 : 0;
#pragma unroll
            for (int o = 16; o > 0; o >>= 1) c2 += __shfl_xor_sync(0xffffffffu, c2, o);
            float coef = (c2 < EXCL && myscore < 0.f) ? 0.f : myscore;
            contrib = coef * myxout;
        }
        spart[wid * FF + lane] = contrib;
        __syncthreads();
        if (wid == 0) {
            float t = 0.f;
#pragma unroll
            for (int q = 0; q < NWARP; ++q) t += spart[q * FF + lane];
            g_part[bid * FF + lane] = t;
        }
        gsync(++epoch);   // B26
    }

    // ---- block 0: final reduce + linear + run-epoch bump ----
    if (bid == 0) {
        float* spart = (float*)(s_raw + 24000);
        float a = 0.f;
        for (int b = wid; b < GRID; b += NWARP) a += __ldcg(g_part + b * FF + lane);
        spart[wid * FF + lane] = a;
        __syncthreads();
        if (wid == 0) {
            float t = 0.f;
#pragma unroll
            for (int q = 0; q < NWARP; ++q) t += spart[q * FF + lane];
            spart[lane] = t * (1.0f / KSELF);
            __syncwarp();
            if (lane < 8) {
                float o = __ldg(lb + lane);
#pragma unroll
                for (int f = 0; f < FF; ++f) o += spart[f] * __ldg(lw + lane * FF + f);
                out[lane] = o;
            }
            if (lane == 0) g_run = gen;
        }
    }
}

// ---------------- host side ----------------
extern "C" void kernel_launch(void* const* d_in, const int* in_sizes, int n_in,
                              void* d_out, int out_size) {
    const float* x     = (const float*)d_in[0];
    const int*   ei    = (const int*)d_in[1];
    const float* h     = (const float*)d_in[2];
    const float* alpha = (const float*)d_in[3];
    const float* Wr0   = (const float*)d_in[4];
    const float* Wc0a  = (const float*)d_in[5];
    const float* Wc0b  = (const float*)d_in[6];
    const float* Wr1   = (const float*)d_in[7];
    const float* Wc1a  = (const float*)d_in[8];
    const float* Wc1b  = (const float*)d_in[9];
    const float* pw    = (const float*)d_in[10];
    const float* lw    = (const float*)d_in[11];
    const float* lb    = (const float*)d_in[12];

    cayley_all<<<GRID, TPB>>>(x, ei, h, alpha, Wr0, Wc0a, Wc0b,
                              Wr1, Wc1a, Wc1b, pw, lw, lb, (float*)d_out);
}